// round 11
// baseline (speedup 1.0000x reference)
#include <cuda_runtime.h>
#include <cuda_fp16.h>
#include <cuda_bf16.h>

#define L   128
#define PD  130                 // padded dim (zero apron)
#define PS  (PD * PD)
#define PV  (PD * PD * PD)

// Oct-packed padded volumes (fp16): one 16B entry per cell = all 8 corners.
//   e.x = half2(v(x0,y0,z0), v(x1,y0,z0)),  e.y = half2(v(x0,y1,z0), v(x1,y1,z0))
//   e.z = half2(v(x0,y0,z1), v(x1,y0,z1)),  e.w = half2(v(x0,y1,z1), v(x1,y1,z1))
// x0=xp-1 etc.; zeros outside the real volume. ONE LDG.128 per trilinear sample.
__device__ uint4 g_oct[4][PV];

__device__ __forceinline__ unsigned pack2(float a, float b) {
    __half2 h = __floats2half2_rn(a, b);
    return *reinterpret_cast<unsigned*>(&h);
}

// Each thread fills 4 consecutive xp entries: per (y,z) row it needs x values
// [xb-1, xb+3] = one aligned float4 + one scalar  ->  8 LDG per 4 entries.
__global__ __launch_bounds__(132)
void fill_oct_kernel(const float* __restrict__ density, int b_base)
{
    const int tc = threadIdx.x;                      // x-chunk 0..32 (xb = 4*tc)
    const int yp = blockIdx.x * 4 + threadIdx.y;     // 0..131
    if (yp >= PD) return;
    const int zp = blockIdx.y;                       // 0..129
    const int b  = b_base + blockIdx.z;

    const int xb = tc * 4;
    const int y0 = yp - 1, z0 = zp - 1;
    const float* volb = density + (size_t)b * L * L * L;

    float w[2][2][5];
    #pragma unroll
    for (int dz = 0; dz < 2; ++dz) {
        const int z = z0 + dz;
        const bool vz = (unsigned)z < (unsigned)L;
        #pragma unroll
        for (int dy = 0; dy < 2; ++dy) {
            const int y = y0 + dy;
            const bool vr = vz && ((unsigned)y < (unsigned)L);
            const float* row = volb + ((size_t)(vz ? z : 0) * L + (vr ? y : 0)) * L;
            float4 q = make_float4(0.f, 0.f, 0.f, 0.f);
            float lf = 0.f;
            if (vr) {
                if (xb <= L - 4) q = __ldg((const float4*)(row + xb)); // aligned
                if (xb >= 1)     lf = __ldg(row + xb - 1);
            }
            w[dz][dy][0] = lf;
            w[dz][dy][1] = q.x; w[dz][dy][2] = q.y;
            w[dz][dy][3] = q.z; w[dz][dy][4] = q.w;
        }
    }

    uint4* dst = &g_oct[b][((size_t)zp * PD + yp) * PD + xb];
    #pragma unroll
    for (int s = 0; s < 4; ++s) {
        if (xb + s < PD) {
            uint4 e;
            e.x = pack2(w[0][0][s], w[0][0][s + 1]);
            e.y = pack2(w[0][1][s], w[0][1][s + 1]);
            e.z = pack2(w[1][0][s], w[1][0][s + 1]);
            e.w = pack2(w[1][1][s], w[1][1][s + 1]);
            dst[s] = e;
        }
    }
}

// Ray-box clip bounds for base (bx,by,bz), dir (dx,dy,dz) against [-1,129]^3.
__device__ __forceinline__ void clip_k(float bx, float by, float bz,
                                       float dx, float dy, float dz,
                                       float& kmin, float& kmax)
{
    kmin = 0.0f; kmax = 127.0f;
    #pragma unroll
    for (int m = 0; m < 3; ++m) {
        const float bm = (m == 0) ? bx : (m == 1) ? by : bz;
        const float rm = (m == 0) ? dx : (m == 1) ? dy : dz;
        if (fabsf(rm) > 1e-9f) {
            const float inv = 1.0f / rm;
            const float t0 = (-1.0f - bm) * inv;
            const float t1 = (129.0f - bm) * inv;
            kmin = fmaxf(kmin, fminf(t0, t1));
            kmax = fminf(kmax, fmaxf(t0, t1));
        } else if (bm <= -1.0f || bm >= 129.0f) {
            kmax = -1.0f;
        }
    }
}

// One trilinear sample from the oct volume (zero-sentinel for out-of-range).
__device__ __forceinline__ float sample_oct(const uint4* __restrict__ oct,
                                            float px, float py, float pz, int ZIDX)
{
    const float fx0 = floorf(px), fy0 = floorf(py), fz0 = floorf(pz);
    const int xp = (int)fx0 + 1;
    const int yp = (int)fy0 + 1;
    const int zp = (int)fz0 + 1;
    const float fx = px - fx0, fy = py - fy0, fz = pz - fz0;

    const unsigned mx = max(max((unsigned)xp, (unsigned)yp), (unsigned)zp);
    int e = (zp * PD + yp) * PD + xp;
    e = (mx <= 129u) ? e : ZIDX;

    const uint4 r = __ldg(oct + e);
    const float2 f00 = __half22float2(*reinterpret_cast<const __half2*>(&r.x));
    const float2 f01 = __half22float2(*reinterpret_cast<const __half2*>(&r.y));
    const float2 f10 = __half22float2(*reinterpret_cast<const __half2*>(&r.z));
    const float2 f11 = __half22float2(*reinterpret_cast<const __half2*>(&r.w));

    const float cx00 = fmaf(fx, f00.y - f00.x, f00.x);
    const float cx10 = fmaf(fx, f01.y - f01.x, f01.x);
    const float c0   = fmaf(fy, cx10 - cx00, cx00);
    const float cx01 = fmaf(fx, f10.y - f10.x, f10.x);
    const float cx11 = fmaf(fx, f11.y - f11.x, f11.x);
    const float c1   = fmaf(fy, cx11 - cx01, cx01);
    return fmaf(fz, c1 - c0, c0);
}

// 2 rays per thread: block handles two adjacent rows along the block axis.
__global__ __launch_bounds__(128)
void proj_kernel(const float* __restrict__ rot,
                 float* __restrict__ out, int bq_base)
{
    const int bq = bq_base + blockIdx.y;
    const int b  = bq >> 3;

    const float* R = rot + bq * 9;
    const float R00 = R[0], R01 = R[1], R02 = R[2];   // i-step
    const float R10 = R[3], R11 = R[4], R12 = R[5];   // j-step
    const float R20 = R[6], R21 = R[7], R22 = R[8];   // k-step (ray dir)

    // Lanes walk the step direction with the smaller (y,z) footprint.
    const bool lanes_j = fmaxf(fabsf(R11), fabsf(R12)) < fmaxf(fabsf(R01), fabsf(R02));
    const int t  = threadIdx.x;          // lane-axis coordinate
    const int jj = blockIdx.x * 2;       // block-axis coordinate (2 rows)

    // Block-axis step vector (per +1 on the block axis)
    const float Dx = lanes_j ? R00 : R10;
    const float Dy = lanes_j ? R01 : R11;
    const float Dz = lanes_j ? R02 : R12;

    const uint4* __restrict__ oct = g_oct[b];
    const int ZIDX = PV - 1;   // cell (129,129,129): all corners zero

    const float cx = 63.5f * (1.0f - (R00 + R10 + R20));
    const float cy = 63.5f * (1.0f - (R01 + R11 + R21));
    const float cz = 63.5f * (1.0f - (R02 + R12 + R22));

    // bases for ray A (block coord jj) and ray B (jj+1)
    float bxA, byA, bzA;
    if (lanes_j) {   // i = block axis, j = lanes
        bxA = fmaf((float)jj, R00, fmaf((float)t, R10, cx));
        byA = fmaf((float)jj, R01, fmaf((float)t, R11, cy));
        bzA = fmaf((float)jj, R02, fmaf((float)t, R12, cz));
    } else {         // i = lanes, j = block axis
        bxA = fmaf((float)t, R00, fmaf((float)jj, R10, cx));
        byA = fmaf((float)t, R01, fmaf((float)jj, R11, cy));
        bzA = fmaf((float)t, R02, fmaf((float)jj, R12, cz));
    }
    const float bxB = bxA + Dx, byB = byA + Dy, bzB = bzA + Dz;

    // union of both rays' k-clips (sentinel keeps all iterations exact)
    float kminA, kmaxA, kminB, kmaxB;
    clip_k(bxA, byA, bzA, R20, R21, R22, kminA, kmaxA);
    clip_k(bxB, byB, bzB, R20, R21, R22, kminB, kmaxB);
    const int k0 = max(0,   (int)floorf(fminf(kminA, kminB)));
    const int k1 = min(127, (int)ceilf (fmaxf(kmaxA, kmaxB)));

    float accA = 0.0f, accB = 0.0f;

    #pragma unroll 4
    for (int k = k0; k <= k1; ++k) {
        const float kf = (float)k;
        const float pxA = fmaf(kf, R20, bxA);
        const float pyA = fmaf(kf, R21, byA);
        const float pzA = fmaf(kf, R22, bzA);
        accA += sample_oct(oct, pxA, pyA, pzA, ZIDX);
        accB += sample_oct(oct, pxA + Dx, pyA + Dy, pzA + Dz, ZIDX);
    }

    // output indices
    const int iA = lanes_j ? jj : t;
    const int jA = lanes_j ? t : jj;
    const int iB = lanes_j ? (jj + 1) : t;
    const int jB = lanes_j ? t : (jj + 1);
    out[((size_t)bq * L + jA) * L + iA] = accA;
    out[((size_t)bq * L + jB) * L + iB] = accB;
}

extern "C" void kernel_launch(void* const* d_in, const int* in_sizes, int n_in,
                              void* d_out, int out_size)
{
    const float* density = (const float*)d_in[0];   // (4,128,128,128)
    const float* rot     = (const float*)d_in[1];   // (4,8,3,3)
    float* out           = (float*)d_out;           // (4,8,128,128)

    // Phase volume pairs: each phase's 70MB oct working set stays L2-resident.
    dim3 fgrid(33, PD, 2);        // yp-tiles, zp, b
    dim3 fblock(33, 4);           // x-chunks, yp-in-tile
    dim3 pgrid(L / 2, 16);        // 2 rows per block

    fill_oct_kernel<<<fgrid, fblock>>>(density, 0);
    proj_kernel<<<pgrid, 128>>>(rot, out, 0);
    fill_oct_kernel<<<fgrid, fblock>>>(density, 2);
    proj_kernel<<<pgrid, 128>>>(rot, out, 16);
}

// round 12
// speedup vs baseline: 1.4307x; 1.4307x over previous
#include <cuda_runtime.h>
#include <cuda_fp16.h>
#include <cuda_bf16.h>

#define L   128
#define PD  130                 // padded dim (zero apron)
#define PS  (PD * PD)
#define PV  (PD * PD * PD)

// Oct-packed padded volumes (fp16): one 16B entry per cell = all 8 corners.
//   e.x = half2(v(x0,y0,z0), v(x1,y0,z0)),  e.y = half2(v(x0,y1,z0), v(x1,y1,z0))
//   e.z = half2(v(x0,y0,z1), v(x1,y0,z1)),  e.w = half2(v(x0,y1,z1), v(x1,y1,z1))
// x0=xp-1 etc.; zeros outside the real volume. ONE LDG.128 per trilinear sample.
__device__ uint4 g_oct[4][PV];

__device__ __forceinline__ unsigned pack2(float a, float b) {
    __half2 h = __floats2half2_rn(a, b);
    return *reinterpret_cast<unsigned*>(&h);
}

// Each thread fills 4 consecutive xp entries: per (y,z) row it needs x values
// [xb-1, xb+3] = one aligned float4 + one scalar  ->  8 LDG per 4 entries.
__global__ __launch_bounds__(132)
void fill_oct_kernel(const float* __restrict__ density)
{
    const int tc = threadIdx.x;                      // x-chunk 0..32 (xb = 4*tc)
    const int yp = blockIdx.x * 4 + threadIdx.y;     // 0..131
    if (yp >= PD) return;
    const int zp = blockIdx.y;                       // 0..129
    const int b  = blockIdx.z;                       // 0..3

    const int xb = tc * 4;
    const int y0 = yp - 1, z0 = zp - 1;
    const float* volb = density + (size_t)b * L * L * L;

    float w[2][2][5];
    #pragma unroll
    for (int dz = 0; dz < 2; ++dz) {
        const int z = z0 + dz;
        const bool vz = (unsigned)z < (unsigned)L;
        #pragma unroll
        for (int dy = 0; dy < 2; ++dy) {
            const int y = y0 + dy;
            const bool vr = vz && ((unsigned)y < (unsigned)L);
            const float* row = volb + ((size_t)(vz ? z : 0) * L + (vr ? y : 0)) * L;
            float4 q = make_float4(0.f, 0.f, 0.f, 0.f);
            float lf = 0.f;
            if (vr) {
                if (xb <= L - 4) q = __ldg((const float4*)(row + xb)); // aligned
                if (xb >= 1)     lf = __ldg(row + xb - 1);
            }
            w[dz][dy][0] = lf;
            w[dz][dy][1] = q.x; w[dz][dy][2] = q.y;
            w[dz][dy][3] = q.z; w[dz][dy][4] = q.w;
        }
    }

    uint4* dst = &g_oct[b][((size_t)zp * PD + yp) * PD + xb];
    #pragma unroll
    for (int s = 0; s < 4; ++s) {
        if (xb + s < PD) {
            uint4 e;
            e.x = pack2(w[0][0][s], w[0][0][s + 1]);
            e.y = pack2(w[0][1][s], w[0][1][s + 1]);
            e.z = pack2(w[1][0][s], w[1][0][s + 1]);
            e.w = pack2(w[1][1][s], w[1][1][s + 1]);
            dst[s] = e;
        }
    }
}

// One trilinear sample from the oct volume (zero-sentinel for out-of-range).
__device__ __forceinline__ float sample_oct(const uint4* __restrict__ oct,
                                            float px, float py, float pz, int ZIDX)
{
    const float fx0 = floorf(px), fy0 = floorf(py), fz0 = floorf(pz);
    const int xp = (int)fx0 + 1;
    const int yp = (int)fy0 + 1;
    const int zp = (int)fz0 + 1;
    const float fx = px - fx0, fy = py - fy0, fz = pz - fz0;

    const unsigned mx = max(max((unsigned)xp, (unsigned)yp), (unsigned)zp);
    int e = (zp * PD + yp) * PD + xp;
    e = (mx <= 129u) ? e : ZIDX;

    const uint4 r = __ldg(oct + e);
    const float2 f00 = __half22float2(*reinterpret_cast<const __half2*>(&r.x));
    const float2 f01 = __half22float2(*reinterpret_cast<const __half2*>(&r.y));
    const float2 f10 = __half22float2(*reinterpret_cast<const __half2*>(&r.z));
    const float2 f11 = __half22float2(*reinterpret_cast<const __half2*>(&r.w));

    const float cx00 = fmaf(fx, f00.y - f00.x, f00.x);
    const float cx10 = fmaf(fx, f01.y - f01.x, f01.x);
    const float c0   = fmaf(fy, cx10 - cx00, cx00);
    const float cx01 = fmaf(fx, f10.y - f10.x, f10.x);
    const float cx11 = fmaf(fx, f11.y - f11.x, f11.x);
    const float c1   = fmaf(fy, cx11 - cx01, cx01);
    return fmaf(fz, c1 - c0, c0);
}

// 1 ray/thread, block = 16x8 output tile (warp = 16x2) for compact warp footprint.
// The 16-wide tile axis follows the in-plane step with the smaller (y,z) footprint.
__global__ __launch_bounds__(128)
void proj_kernel(const float* __restrict__ rot,
                 float* __restrict__ out)
{
    const int bq = blockIdx.z;      // 0..31
    const int b  = bq >> 3;

    const float* R = rot + bq * 9;
    const float R00 = R[0], R01 = R[1], R02 = R[2];   // i-step
    const float R10 = R[3], R11 = R[4], R12 = R[5];   // j-step
    const float R20 = R[6], R21 = R[7], R22 = R[8];   // k-step (ray dir)

    // A-axis = in-plane step with smaller (y,z) footprint (gets the 16-wide dim).
    const bool A_is_j = fmaxf(fabsf(R11), fabsf(R12)) < fmaxf(fabsf(R01), fabsf(R02));

    const int t = threadIdx.x;
    const int u = blockIdx.x * 16 + (t & 15);   // A-coord (0..127)
    const int v = blockIdx.y * 8  + (t >> 4);   // B-coord (0..127)

    const int i = A_is_j ? v : u;
    const int j = A_is_j ? u : v;

    const uint4* __restrict__ oct = g_oct[b];
    const int ZIDX = PV - 1;   // cell (129,129,129): all corners zero

    const float bx = fmaf((float)i, R00, fmaf((float)j, R10, 63.5f * (1.0f - (R00 + R10 + R20))));
    const float by = fmaf((float)i, R01, fmaf((float)j, R11, 63.5f * (1.0f - (R01 + R11 + R21))));
    const float bz = fmaf((float)i, R02, fmaf((float)j, R12, 63.5f * (1.0f - (R02 + R12 + R22))));

    // Ray-box clip (perf only; sentinel keeps every iteration exact).
    float kmin = 0.0f, kmax = 127.0f;
    {
        #pragma unroll
        for (int m = 0; m < 3; ++m) {
            const float bm = (m == 0) ? bx : (m == 1) ? by : bz;
            const float rm = (m == 0) ? R20 : (m == 1) ? R21 : R22;
            if (fabsf(rm) > 1e-9f) {
                const float inv = 1.0f / rm;
                const float t0 = (-1.0f - bm) * inv;
                const float t1 = (129.0f - bm) * inv;
                kmin = fmaxf(kmin, fminf(t0, t1));
                kmax = fminf(kmax, fmaxf(t0, t1));
            } else if (bm <= -1.0f || bm >= 129.0f) {
                kmax = -1.0f;
            }
        }
    }
    const int k0 = max(0,   (int)floorf(kmin));
    const int k1 = min(127, (int)ceilf(kmax));

    float acc = 0.0f;

    #pragma unroll 4
    for (int k = k0; k <= k1; ++k) {
        const float kf = (float)k;
        const float px = fmaf(kf, R20, bx);
        const float py = fmaf(kf, R21, by);
        const float pz = fmaf(kf, R22, bz);
        acc += sample_oct(oct, px, py, pz, ZIDX);
    }

    out[((size_t)bq * L + j) * L + i] = acc;
}

extern "C" void kernel_launch(void* const* d_in, const int* in_sizes, int n_in,
                              void* d_out, int out_size)
{
    const float* density = (const float*)d_in[0];   // (4,128,128,128)
    const float* rot     = (const float*)d_in[1];   // (4,8,3,3)
    float* out           = (float*)d_out;           // (4,8,128,128)

    dim3 fgrid(33, PD, 4);        // yp-tiles, zp, b — one fill launch
    dim3 fblock(33, 4);
    dim3 pgrid(8, 16, 32);        // A-tiles, B-tiles, bq — one proj launch

    fill_oct_kernel<<<fgrid, fblock>>>(density);
    proj_kernel<<<pgrid, 128>>>(rot, out);
}

// round 13
// speedup vs baseline: 1.6451x; 1.1498x over previous
#include <cuda_runtime.h>
#include <cuda_fp16.h>
#include <cuda_bf16.h>

#define L    128
#define PD   130                 // padded x,y dims (zero apron)
#define PDZ  131                 // padded z-plane count (zq = 0..130 -> z = -1..129)
#define PS   (PD * PD)           // plane stride (entries)
#define PVQ  (PDZ * PD * PD)     // quad volume entries

// Quad-packed padded volumes (fp16), 8B/entry, L2-RESIDENT (71MB total):
//   g_quad[b][(zq*PD+yp)*PD+xp] = { half2(v(x0,y0,z), v(x1,y0,z)),
//                                   half2(v(x0,y1,z), v(x1,y1,z)) }
// with x0=xp-1, y0=yp-1, z=zq-1; zeros outside the real volume.
// A trilinear sample = 2 x LDG.64 (planes zq, zq+1).
__device__ uint2 g_quad[4][PVQ];

__device__ __forceinline__ unsigned pack2(float a, float b) {
    __half2 h = __floats2half2_rn(a, b);
    return *reinterpret_cast<unsigned*>(&h);
}

// Each thread fills 4 consecutive xp entries at one (yp, zq):
// needs rows y0,y0+1 of plane z = zq-1, x window [xb-1, xb+3]
// = 2 aligned float4 + 2 scalars -> 4 LDG per 4 entries.
__global__ __launch_bounds__(132)
void fill_quad_kernel(const float* __restrict__ density)
{
    const int tc = threadIdx.x;                      // x-chunk 0..32 (xb = 4*tc)
    const int yp = blockIdx.x * 4 + threadIdx.y;     // 0..131
    if (yp >= PD) return;
    const int zq = blockIdx.y;                       // 0..130
    const int b  = blockIdx.z;                       // 0..3

    const int xb = tc * 4;
    const int y0 = yp - 1, z = zq - 1;
    const float* volb = density + (size_t)b * L * L * L;
    const bool vz = (unsigned)z < (unsigned)L;

    // w[dy][0..4] = v(xb-1 .. xb+3) for rows y0, y0+1 at plane z.
    float w[2][5];
    #pragma unroll
    for (int dy = 0; dy < 2; ++dy) {
        const int y = y0 + dy;
        const bool vr = vz && ((unsigned)y < (unsigned)L);
        const float* row = volb + ((size_t)(vz ? z : 0) * L + (vr ? y : 0)) * L;
        float4 q = make_float4(0.f, 0.f, 0.f, 0.f);
        float lf = 0.f;
        if (vr) {
            if (xb <= L - 4) q = __ldg((const float4*)(row + xb)); // aligned
            if (xb >= 1)     lf = __ldg(row + xb - 1);
        }
        w[dy][0] = lf;
        w[dy][1] = q.x; w[dy][2] = q.y;
        w[dy][3] = q.z; w[dy][4] = q.w;
    }

    uint2* dst = &g_quad[b][((size_t)zq * PD + yp) * PD + xb];
    #pragma unroll
    for (int s = 0; s < 4; ++s) {
        if (xb + s < PD) {
            uint2 e;
            e.x = pack2(w[0][s], w[0][s + 1]);
            e.y = pack2(w[1][s], w[1][s + 1]);
            dst[s] = e;
        }
    }
}

// One trilinear sample (zero-sentinel redirect for out-of-range; the sentinel
// entry and the entry one plane above it are both all-zero apron cells).
__device__ __forceinline__ float sample_quad(const uint2* __restrict__ quad,
                                             float px, float py, float pz, int ZIDX)
{
    const float fx0 = floorf(px), fy0 = floorf(py), fz0 = floorf(pz);
    const int xp = (int)fx0 + 1;
    const int yp = (int)fy0 + 1;
    const int zq = (int)fz0 + 1;
    const float fx = px - fx0, fy = py - fy0, fz = pz - fz0;

    const unsigned mx = max(max((unsigned)xp, (unsigned)yp), (unsigned)zq);
    int e = (zq * PD + yp) * PD + xp;
    e = (mx <= 129u) ? e : ZIDX;     // valid e has zq<=129 -> e+PS in bounds

    const uint2 r0 = __ldg(quad + e);        // plane zq   : (v000,v100),(v010,v110)
    const uint2 r1 = __ldg(quad + e + PS);   // plane zq+1 : (v001,v101),(v011,v111)

    const float2 f00 = __half22float2(*reinterpret_cast<const __half2*>(&r0.x));
    const float2 f01 = __half22float2(*reinterpret_cast<const __half2*>(&r0.y));
    const float2 f10 = __half22float2(*reinterpret_cast<const __half2*>(&r1.x));
    const float2 f11 = __half22float2(*reinterpret_cast<const __half2*>(&r1.y));

    const float cx00 = fmaf(fx, f00.y - f00.x, f00.x);
    const float cx10 = fmaf(fx, f01.y - f01.x, f01.x);
    const float c0   = fmaf(fy, cx10 - cx00, cx00);
    const float cx01 = fmaf(fx, f10.y - f10.x, f10.x);
    const float cx11 = fmaf(fx, f11.y - f11.x, f11.x);
    const float c1   = fmaf(fy, cx11 - cx01, cx01);
    return fmaf(fz, c1 - c0, c0);
}

// 1 ray/thread, block = 16x8 output tile (warp = 16x2); the 16-wide axis
// follows the in-plane step with the smaller (y,z) footprint.
__global__ __launch_bounds__(128)
void proj_kernel(const float* __restrict__ rot,
                 float* __restrict__ out)
{
    const int bq = blockIdx.z;      // 0..31
    const int b  = bq >> 3;

    const float* R = rot + bq * 9;
    const float R00 = R[0], R01 = R[1], R02 = R[2];   // i-step
    const float R10 = R[3], R11 = R[4], R12 = R[5];   // j-step
    const float R20 = R[6], R21 = R[7], R22 = R[8];   // k-step (ray dir)

    const bool A_is_j = fmaxf(fabsf(R11), fabsf(R12)) < fmaxf(fabsf(R01), fabsf(R02));

    const int t = threadIdx.x;
    const int u = blockIdx.x * 16 + (t & 15);   // A-coord
    const int v = blockIdx.y * 8  + (t >> 4);   // B-coord

    const int i = A_is_j ? v : u;
    const int j = A_is_j ? u : v;

    const uint2* __restrict__ quad = g_quad[b];
    // Sentinel: plane zq=0 (z=-1), xp=yp=129 -> all-zero; +PS also all-zero apron.
    const int ZIDX = 129 * PD + 129;

    const float bx = fmaf((float)i, R00, fmaf((float)j, R10, 63.5f * (1.0f - (R00 + R10 + R20))));
    const float by = fmaf((float)i, R01, fmaf((float)j, R11, 63.5f * (1.0f - (R01 + R11 + R21))));
    const float bz = fmaf((float)i, R02, fmaf((float)j, R12, 63.5f * (1.0f - (R02 + R12 + R22))));

    // Ray-box clip (perf only; sentinel keeps every iteration exact).
    float kmin = 0.0f, kmax = 127.0f;
    {
        #pragma unroll
        for (int m = 0; m < 3; ++m) {
            const float bm = (m == 0) ? bx : (m == 1) ? by : bz;
            const float rm = (m == 0) ? R20 : (m == 1) ? R21 : R22;
            if (fabsf(rm) > 1e-9f) {
                const float inv = 1.0f / rm;
                const float t0 = (-1.0f - bm) * inv;
                const float t1 = (129.0f - bm) * inv;
                kmin = fmaxf(kmin, fminf(t0, t1));
                kmax = fminf(kmax, fmaxf(t0, t1));
            } else if (bm <= -1.0f || bm >= 129.0f) {
                kmax = -1.0f;
            }
        }
    }
    const int k0 = max(0,   (int)floorf(kmin));
    const int k1 = min(127, (int)ceilf(kmax));

    float acc = 0.0f;

    #pragma unroll 4
    for (int k = k0; k <= k1; ++k) {
        const float kf = (float)k;
        const float px = fmaf(kf, R20, bx);
        const float py = fmaf(kf, R21, by);
        const float pz = fmaf(kf, R22, bz);
        acc += sample_quad(quad, px, py, pz, ZIDX);
    }

    out[((size_t)bq * L + j) * L + i] = acc;
}

extern "C" void kernel_launch(void* const* d_in, const int* in_sizes, int n_in,
                              void* d_out, int out_size)
{
    const float* density = (const float*)d_in[0];   // (4,128,128,128)
    const float* rot     = (const float*)d_in[1];   // (4,8,3,3)
    float* out           = (float*)d_out;           // (4,8,128,128)

    dim3 fgrid(33, PDZ, 4);       // yp-tiles, zq, b — one fill launch
    dim3 fblock(33, 4);
    dim3 pgrid(8, 16, 32);        // A-tiles, B-tiles, bq — one proj launch

    fill_quad_kernel<<<fgrid, fblock>>>(density);
    proj_kernel<<<pgrid, 128>>>(rot, out);
}

// round 16
// speedup vs baseline: 1.6805x; 1.0215x over previous
#include <cuda_runtime.h>
#include <cuda_fp16.h>
#include <cuda_bf16.h>

#define L    128
#define PD   130                 // padded x,y dims (zero apron)
#define PDZ  131                 // padded z-plane count (zq = 0..130 -> z = -1..129)
#define PS   (PD * PD)           // plane stride (entries)
#define PVQ  (PDZ * PD * PD)     // quad volume entries

// Quad-packed padded volumes (fp16), 8B/entry, L2-RESIDENT (71MB total):
//   g_quad[b][(zq*PD+yp)*PD+xp] = { half2(v(x0,y0,z), v(x1,y0,z)),
//                                   half2(v(x0,y1,z), v(x1,y1,z)) }
// with x0=xp-1, y0=yp-1, z=zq-1; zeros outside the real volume.
// A trilinear sample = 2 x LDG.64 (planes zq, zq+1).
__device__ uint2 g_quad[4][PVQ];

__device__ __forceinline__ unsigned pack2(float a, float b) {
    __half2 h = __floats2half2_rn(a, b);
    return *reinterpret_cast<unsigned*>(&h);
}

// Each thread fills 4 consecutive xp entries at one (yp, zq).
__global__ __launch_bounds__(132)
void fill_quad_kernel(const float* __restrict__ density)
{
    const int tc = threadIdx.x;                      // x-chunk 0..32 (xb = 4*tc)
    const int yp = blockIdx.x * 4 + threadIdx.y;     // 0..131
    if (yp >= PD) return;
    const int zq = blockIdx.y;                       // 0..130
    const int b  = blockIdx.z;                       // 0..3

    const int xb = tc * 4;
    const int y0 = yp - 1, z = zq - 1;
    const float* volb = density + (size_t)b * L * L * L;
    const bool vz = (unsigned)z < (unsigned)L;

    float w[2][5];
    #pragma unroll
    for (int dy = 0; dy < 2; ++dy) {
        const int y = y0 + dy;
        const bool vr = vz && ((unsigned)y < (unsigned)L);
        const float* row = volb + ((size_t)(vz ? z : 0) * L + (vr ? y : 0)) * L;
        float4 q = make_float4(0.f, 0.f, 0.f, 0.f);
        float lf = 0.f;
        if (vr) {
            if (xb <= L - 4) q = __ldg((const float4*)(row + xb)); // aligned
            if (xb >= 1)     lf = __ldg(row + xb - 1);
        }
        w[dy][0] = lf;
        w[dy][1] = q.x; w[dy][2] = q.y;
        w[dy][3] = q.z; w[dy][4] = q.w;
    }

    uint2* dst = &g_quad[b][((size_t)zq * PD + yp) * PD + xb];
    #pragma unroll
    for (int s = 0; s < 4; ++s) {
        if (xb + s < PD) {
            uint2 e;
            e.x = pack2(w[0][s], w[0][s + 1]);
            e.y = pack2(w[1][s], w[1][s + 1]);
            dst[s] = e;
        }
    }
}

// 1 ray/thread, block = 16x8 output tile (warp = 16x2). Batch-4 software
// pipeline: 4 indices -> 8 back-to-back LDG.64 -> 4 interps (MLP 8/warp).
__global__ __launch_bounds__(128)
void proj_kernel(const float* __restrict__ rot,
                 float* __restrict__ out)
{
    const int bq = blockIdx.z;      // 0..31
    const int b  = bq >> 3;

    const float* R = rot + bq * 9;
    const float R00 = R[0], R01 = R[1], R02 = R[2];   // i-step
    const float R10 = R[3], R11 = R[4], R12 = R[5];   // j-step
    const float R20 = R[6], R21 = R[7], R22 = R[8];   // k-step (ray dir)

    const bool A_is_j = fmaxf(fabsf(R11), fabsf(R12)) < fmaxf(fabsf(R01), fabsf(R02));

    const int t = threadIdx.x;
    const int u = blockIdx.x * 16 + (t & 15);   // A-coord
    const int v = blockIdx.y * 8  + (t >> 4);   // B-coord

    const int i = A_is_j ? v : u;
    const int j = A_is_j ? u : v;

    const uint2* __restrict__ quad = g_quad[b];
    // Sentinel: plane zq=0 (z=-1), xp=yp=129 -> all-zero; +PS also all-zero apron.
    const int ZIDX = 129 * PD + 129;

    const float bx = fmaf((float)i, R00, fmaf((float)j, R10, 63.5f * (1.0f - (R00 + R10 + R20))));
    const float by = fmaf((float)i, R01, fmaf((float)j, R11, 63.5f * (1.0f - (R01 + R11 + R21))));
    const float bz = fmaf((float)i, R02, fmaf((float)j, R12, 63.5f * (1.0f - (R02 + R12 + R22))));

    // Ray-box clip (perf only; sentinel keeps every iteration exact).
    float kmin = 0.0f, kmax = 127.0f;
    {
        #pragma unroll
        for (int m = 0; m < 3; ++m) {
            const float bm = (m == 0) ? bx : (m == 1) ? by : bz;
            const float rm = (m == 0) ? R20 : (m == 1) ? R21 : R22;
            if (fabsf(rm) > 1e-9f) {
                const float inv = 1.0f / rm;
                const float t0 = (-1.0f - bm) * inv;
                const float t1 = (129.0f - bm) * inv;
                kmin = fmaxf(kmin, fminf(t0, t1));
                kmax = fminf(kmax, fmaxf(t0, t1));
            } else if (bm <= -1.0f || bm >= 129.0f) {
                kmax = -1.0f;
            }
        }
    }
    const int k0 = max(0,   (int)floorf(kmin));
    const int k1 = min(127, (int)ceilf(kmax));

    float acc = 0.0f;

    for (int kb = k0; kb <= k1; kb += 4) {
        int   eidx[4];
        float wx[4], wy[4], wz[4];

        // Phase 1: indices + weights for 4 samples. Samples past k1 (or out of
        // the box) are redirected to the all-zero sentinel -> contribute 0.
        #pragma unroll
        for (int s = 0; s < 4; ++s) {
            const float kf = (float)(kb + s);
            const float px = fmaf(kf, R20, bx);
            const float py = fmaf(kf, R21, by);
            const float pz = fmaf(kf, R22, bz);

            const float fx0 = floorf(px), fy0 = floorf(py), fz0 = floorf(pz);
            const int xp = (int)fx0 + 1;
            const int yp = (int)fy0 + 1;
            const int zq = (int)fz0 + 1;
            wx[s] = px - fx0; wy[s] = py - fy0; wz[s] = pz - fz0;

            const unsigned mx = max(max((unsigned)xp, (unsigned)yp), (unsigned)zq);
            const bool ok = (mx <= 129u) && (kb + s <= k1);
            const int e = (zq * PD + yp) * PD + xp;
            eidx[s] = ok ? e : ZIDX;
        }

        // Phase 2: issue all 8 loads back-to-back.
        uint2 ra[4], rb[4];
        #pragma unroll
        for (int s = 0; s < 4; ++s) {
            ra[s] = __ldg(quad + eidx[s]);        // plane zq
            rb[s] = __ldg(quad + eidx[s] + PS);   // plane zq+1
        }

        // Phase 3: consume.
        #pragma unroll
        for (int s = 0; s < 4; ++s) {
            const float2 f00 = __half22float2(*reinterpret_cast<const __half2*>(&ra[s].x));
            const float2 f01 = __half22float2(*reinterpret_cast<const __half2*>(&ra[s].y));
            const float2 f10 = __half22float2(*reinterpret_cast<const __half2*>(&rb[s].x));
            const float2 f11 = __half22float2(*reinterpret_cast<const __half2*>(&rb[s].y));

            const float cx00 = fmaf(wx[s], f00.y - f00.x, f00.x);
            const float cx10 = fmaf(wx[s], f01.y - f01.x, f01.x);
            const float c0   = fmaf(wy[s], cx10 - cx00, cx00);
            const float cx01 = fmaf(wx[s], f10.y - f10.x, f10.x);
            const float cx11 = fmaf(wx[s], f11.y - f11.x, f11.x);
            const float c1   = fmaf(wy[s], cx11 - cx01, cx01);
            acc += fmaf(wz[s], c1 - c0, c0);
        }
    }

    out[((size_t)bq * L + j) * L + i] = acc;
}

extern "C" void kernel_launch(void* const* d_in, const int* in_sizes, int n_in,
                              void* d_out, int out_size)
{
    const float* density = (const float*)d_in[0];   // (4,128,128,128)
    const float* rot     = (const float*)d_in[1];   // (4,8,3,3)
    float* out           = (float*)d_out;           // (4,8,128,128)

    dim3 fgrid(33, PDZ, 4);       // yp-tiles, zq, b — one fill launch
    dim3 fblock(33, 4);
    dim3 pgrid(8, 16, 32);        // A-tiles, B-tiles, bq — one proj launch

    fill_quad_kernel<<<fgrid, fblock>>>(density);
    proj_kernel<<<pgrid, 128>>>(rot, out);
}

// round 17
// speedup vs baseline: 1.9056x; 1.1340x over previous
#include <cuda_runtime.h>
#include <cuda_fp16.h>
#include <cuda_bf16.h>

#define L    128
#define PD   130                 // padded x,y dims (zero apron)
#define PDZ  131                 // padded z-plane count (zq = 0..130 -> z = -1..129)
#define PS   (PD * PD)           // plane stride (entries)
#define PVQ  (PDZ * PD * PD)     // quad volume entries

// Quad-packed padded volumes (fp16), 8B/entry, L2-RESIDENT (71MB total):
//   g_quad[b][(zq*PD+yp)*PD+xp] = { half2(v(x0,y0,z), v(x1,y0,z)),
//                                   half2(v(x0,y1,z), v(x1,y1,z)) }
// with x0=xp-1, y0=yp-1, z=zq-1; zeros outside the real volume.
// A trilinear sample = 2 x LDG.64 (planes zq, zq+1).
__device__ uint2 g_quad[4][PVQ];

__device__ __forceinline__ unsigned pack2(float a, float b) {
    __half2 h = __floats2half2_rn(a, b);
    return *reinterpret_cast<unsigned*>(&h);
}

// Each thread fills 4 consecutive xp entries at one (yp, zq).
__global__ __launch_bounds__(132)
void fill_quad_kernel(const float* __restrict__ density)
{
    const int tc = threadIdx.x;                      // x-chunk 0..32 (xb = 4*tc)
    const int yp = blockIdx.x * 4 + threadIdx.y;     // 0..131
    if (yp >= PD) return;
    const int zq = blockIdx.y;                       // 0..130
    const int b  = blockIdx.z;                       // 0..3

    const int xb = tc * 4;
    const int y0 = yp - 1, z = zq - 1;
    const float* volb = density + (size_t)b * L * L * L;
    const bool vz = (unsigned)z < (unsigned)L;

    float w[2][5];
    #pragma unroll
    for (int dy = 0; dy < 2; ++dy) {
        const int y = y0 + dy;
        const bool vr = vz && ((unsigned)y < (unsigned)L);
        const float* row = volb + ((size_t)(vz ? z : 0) * L + (vr ? y : 0)) * L;
        float4 q = make_float4(0.f, 0.f, 0.f, 0.f);
        float lf = 0.f;
        if (vr) {
            if (xb <= L - 4) q = __ldg((const float4*)(row + xb)); // aligned
            if (xb >= 1)     lf = __ldg(row + xb - 1);
        }
        w[dy][0] = lf;
        w[dy][1] = q.x; w[dy][2] = q.y;
        w[dy][3] = q.z; w[dy][4] = q.w;
    }

    uint2* dst = &g_quad[b][((size_t)zq * PD + yp) * PD + xb];
    #pragma unroll
    for (int s = 0; s < 4; ++s) {
        if (xb + s < PD) {
            uint2 e;
            e.x = pack2(w[0][s], w[0][s + 1]);
            e.y = pack2(w[1][s], w[1][s + 1]);
            dst[s] = e;
        }
    }
}

// Pad-offset constant folded into the flat index: (+1,+1,+1) in (z,y,x).
#define EOFF ((PD + 1) * PD + 1)

// 1 ray/thread. Block tile = 16x8, warp sub-tile = 8x4 (compact footprint).
// Batch-4 pipeline: 4 indices -> 8 back-to-back LDG.64 -> 4 interps.
// launch_bounds(128, 8): allow up to 64 regs so the batch stays in flight.
__global__ __launch_bounds__(128, 8)
void proj_kernel(const float* __restrict__ rot,
                 float* __restrict__ out)
{
    const int bq = blockIdx.z;      // 0..31
    const int b  = bq >> 3;

    const float* R = rot + bq * 9;
    const float R00 = R[0], R01 = R[1], R02 = R[2];   // i-step
    const float R10 = R[3], R11 = R[4], R12 = R[5];   // j-step
    const float R20 = R[6], R21 = R[7], R22 = R[8];   // k-step (ray dir)

    const bool A_is_j = fmaxf(fabsf(R11), fabsf(R12)) < fmaxf(fabsf(R01), fabsf(R02));

    // warp = 8x4 sub-tile; 4 warps arranged 2x2 inside the 16x8 block tile
    const int t    = threadIdx.x;
    const int wrp  = t >> 5;
    const int lane = t & 31;
    const int u = blockIdx.x * 16 + (wrp & 1) * 8 + (lane & 7);          // A-coord
    const int v = blockIdx.y * 8  + (wrp >> 1) * 4 + ((lane >> 3) & 3);  // B-coord

    const int i = A_is_j ? v : u;
    const int j = A_is_j ? u : v;

    const uint2* __restrict__ quad = g_quad[b];
    // Sentinel: plane zq=0 (z=-1), xp=yp=129 -> all-zero; +PS also all-zero apron.
    const int ZIDX = 129 * PD + 129;

    const float bx = fmaf((float)i, R00, fmaf((float)j, R10, 63.5f * (1.0f - (R00 + R10 + R20))));
    const float by = fmaf((float)i, R01, fmaf((float)j, R11, 63.5f * (1.0f - (R01 + R11 + R21))));
    const float bz = fmaf((float)i, R02, fmaf((float)j, R12, 63.5f * (1.0f - (R02 + R12 + R22))));

    // Ray-box clip (perf only; sentinel keeps every iteration exact).
    float kmin = 0.0f, kmax = 127.0f;
    {
        #pragma unroll
        for (int m = 0; m < 3; ++m) {
            const float bm = (m == 0) ? bx : (m == 1) ? by : bz;
            const float rm = (m == 0) ? R20 : (m == 1) ? R21 : R22;
            if (fabsf(rm) > 1e-9f) {
                const float inv = 1.0f / rm;
                const float t0 = (-1.0f - bm) * inv;
                const float t1 = (129.0f - bm) * inv;
                kmin = fmaxf(kmin, fminf(t0, t1));
                kmax = fminf(kmax, fmaxf(t0, t1));
            } else if (bm <= -1.0f || bm >= 129.0f) {
                kmax = -1.0f;
            }
        }
    }
    const int k0 = max(0,   (int)floorf(kmin));
    const int k1 = min(127, (int)ceilf(kmax));

    float acc = 0.0f;

    for (int kb = k0; kb <= k1; kb += 4) {
        int   eidx[4];
        float wx[4], wy[4], wz[4];

        // Phase 1: indices + weights. Out-of-box or past-k1 samples redirect
        // to the all-zero sentinel -> contribute exactly 0.
        #pragma unroll
        for (int s = 0; s < 4; ++s) {
            const float kf = (float)(kb + s);
            const float px = fmaf(kf, R20, bx);
            const float py = fmaf(kf, R21, by);
            const float pz = fmaf(kf, R22, bz);

            const float fx0 = floorf(px), fy0 = floorf(py), fz0 = floorf(pz);
            const int x0 = (int)fx0, y0 = (int)fy0, z0 = (int)fz0;
            wx[s] = px - fx0; wy[s] = py - fy0; wz[s] = pz - fz0;

            // valid iff x0,y0,z0 all in [-1,128]  <=>  (unsigned)(c+1) <= 129
            const unsigned mx = max(max((unsigned)(x0 + 1), (unsigned)(y0 + 1)),
                                    (unsigned)(z0 + 1));
            const bool ok = (mx <= 129u) && (kb + s <= k1);
            const int e = (z0 * PD + y0) * PD + x0 + EOFF;
            eidx[s] = ok ? e : ZIDX;
        }

        // Phase 2: issue all 8 loads back-to-back.
        uint2 ra[4], rb[4];
        #pragma unroll
        for (int s = 0; s < 4; ++s) {
            ra[s] = __ldg(quad + eidx[s]);        // plane zq
            rb[s] = __ldg(quad + eidx[s] + PS);   // plane zq+1
        }

        // Phase 3: consume.
        #pragma unroll
        for (int s = 0; s < 4; ++s) {
            const float2 f00 = __half22float2(*reinterpret_cast<const __half2*>(&ra[s].x));
            const float2 f01 = __half22float2(*reinterpret_cast<const __half2*>(&ra[s].y));
            const float2 f10 = __half22float2(*reinterpret_cast<const __half2*>(&rb[s].x));
            const float2 f11 = __half22float2(*reinterpret_cast<const __half2*>(&rb[s].y));

            const float cx00 = fmaf(wx[s], f00.y - f00.x, f00.x);
            const float cx10 = fmaf(wx[s], f01.y - f01.x, f01.x);
            const float c0   = fmaf(wy[s], cx10 - cx00, cx00);
            const float cx01 = fmaf(wx[s], f10.y - f10.x, f10.x);
            const float cx11 = fmaf(wx[s], f11.y - f11.x, f11.x);
            const float c1   = fmaf(wy[s], cx11 - cx01, cx01);
            acc += fmaf(wz[s], c1 - c0, c0);
        }
    }

    out[((size_t)bq * L + j) * L + i] = acc;
}

extern "C" void kernel_launch(void* const* d_in, const int* in_sizes, int n_in,
                              void* d_out, int out_size)
{
    const float* density = (const float*)d_in[0];   // (4,128,128,128)
    const float* rot     = (const float*)d_in[1];   // (4,8,3,3)
    float* out           = (float*)d_out;           // (4,8,128,128)

    dim3 fgrid(33, PDZ, 4);       // yp-tiles, zq, b — one fill launch
    dim3 fblock(33, 4);
    dim3 pgrid(8, 16, 32);        // A-tiles, B-tiles, bq — one proj launch

    fill_quad_kernel<<<fgrid, fblock>>>(density);
    proj_kernel<<<pgrid, 128>>>(rot, out);
}